// round 2
// baseline (speedup 1.0000x reference)
#include <cuda_runtime.h>

#define NB 32768
#define DD 1024
#define HH 256

// Scratch (no allocations allowed): h1 = relu(F@Wg1+b)  [32768,256]
// comp = clipped gated features                          [32768,1024]
__device__ float g_h1[(size_t)NB * HH];
__device__ float g_comp[(size_t)NB * DD];

// ---------------------------------------------------------------------------
// GEMM1: h1 = relu(F[32768,1024] @ Wg1[1024,256] + b_g1)
// Tiling: 128x64 block tile, BK=16, 256 threads, 8x4 per-thread microtile.
// ---------------------------------------------------------------------------
__global__ __launch_bounds__(256) void k_gemm1(const float* __restrict__ A,
                                               const float* __restrict__ W,
                                               const float* __restrict__ bias)
{
    const int K = DD, N = HH;
    __shared__ float As[16 * 128];   // [k][m]
    __shared__ float Bs[16 * 64];    // [k][n]
    const int tid = threadIdx.x;
    const int tx = tid & 15, ty = tid >> 4;
    const int bm0 = blockIdx.y * 128;
    const int bn0 = blockIdx.x * 64;

    float acc[8][4];
#pragma unroll
    for (int m = 0; m < 8; m++)
#pragma unroll
        for (int n = 0; n < 4; n++) acc[m][n] = 0.f;

    // A tile loader: thread -> row (tid>>1), 8 consecutive cols at (tid&1)*8
    const int ar = tid >> 1;
    const int acb = (tid & 1) * 8;
    // B tile loader: one float4 per thread
    const int br = tid >> 4;        // 0..15 (k within tile)
    const int bc4 = (tid & 15) * 4; // col within tile

    for (int k0 = 0; k0 < K; k0 += 16) {
        const float* ap = A + (size_t)(bm0 + ar) * K + k0 + acb;
        float4 v0 = *(const float4*)(ap);
        float4 v1 = *(const float4*)(ap + 4);
        As[(acb + 0) * 128 + ar] = v0.x;
        As[(acb + 1) * 128 + ar] = v0.y;
        As[(acb + 2) * 128 + ar] = v0.z;
        As[(acb + 3) * 128 + ar] = v0.w;
        As[(acb + 4) * 128 + ar] = v1.x;
        As[(acb + 5) * 128 + ar] = v1.y;
        As[(acb + 6) * 128 + ar] = v1.z;
        As[(acb + 7) * 128 + ar] = v1.w;
        *(float4*)(Bs + br * 64 + bc4) =
            *(const float4*)(W + (size_t)(k0 + br) * N + bn0 + bc4);
        __syncthreads();
#pragma unroll
        for (int k = 0; k < 16; k++) {
            float a[8], b[4];
#pragma unroll
            for (int m = 0; m < 8; m++) a[m] = As[k * 128 + ty * 8 + m];
#pragma unroll
            for (int n = 0; n < 4; n++) b[n] = Bs[k * 64 + tx * 4 + n];
#pragma unroll
            for (int m = 0; m < 8; m++)
#pragma unroll
                for (int n = 0; n < 4; n++) acc[m][n] = fmaf(a[m], b[n], acc[m][n]);
        }
        __syncthreads();
    }

    const int col = bn0 + tx * 4;
    float4 bb = *(const float4*)(bias + col);
#pragma unroll
    for (int m = 0; m < 8; m++) {
        int row = bm0 + ty * 8 + m;
        float4 o;
        o.x = fmaxf(acc[m][0] + bb.x, 0.f);
        o.y = fmaxf(acc[m][1] + bb.y, 0.f);
        o.z = fmaxf(acc[m][2] + bb.z, 0.f);
        o.w = fmaxf(acc[m][3] + bb.w, 0.f);
        *(float4*)(g_h1 + (size_t)row * N + col) = o;
    }
}

// ---------------------------------------------------------------------------
// GEMM2 + fused epilogue:
//   gw    = sigmoid(h1[32768,256] @ Wg2[256,1024] + b_g2)
//   gated = F * gw
//   comp  = (gated > 0.3) ? 0 : gated          (competition path is dead code)
// ---------------------------------------------------------------------------
__global__ __launch_bounds__(256) void k_gemm2(const float* __restrict__ F,
                                               const float* __restrict__ W,
                                               const float* __restrict__ bias)
{
    const int K = HH, N = DD;
    __shared__ float As[16 * 128];
    __shared__ float Bs[16 * 64];
    const int tid = threadIdx.x;
    const int tx = tid & 15, ty = tid >> 4;
    const int bm0 = blockIdx.y * 128;
    const int bn0 = blockIdx.x * 64;

    float acc[8][4];
#pragma unroll
    for (int m = 0; m < 8; m++)
#pragma unroll
        for (int n = 0; n < 4; n++) acc[m][n] = 0.f;

    const int ar = tid >> 1;
    const int acb = (tid & 1) * 8;
    const int br = tid >> 4;
    const int bc4 = (tid & 15) * 4;

    for (int k0 = 0; k0 < K; k0 += 16) {
        const float* ap = g_h1 + (size_t)(bm0 + ar) * K + k0 + acb;
        float4 v0 = *(const float4*)(ap);
        float4 v1 = *(const float4*)(ap + 4);
        As[(acb + 0) * 128 + ar] = v0.x;
        As[(acb + 1) * 128 + ar] = v0.y;
        As[(acb + 2) * 128 + ar] = v0.z;
        As[(acb + 3) * 128 + ar] = v0.w;
        As[(acb + 4) * 128 + ar] = v1.x;
        As[(acb + 5) * 128 + ar] = v1.y;
        As[(acb + 6) * 128 + ar] = v1.z;
        As[(acb + 7) * 128 + ar] = v1.w;
        *(float4*)(Bs + br * 64 + bc4) =
            *(const float4*)(W + (size_t)(k0 + br) * N + bn0 + bc4);
        __syncthreads();
#pragma unroll
        for (int k = 0; k < 16; k++) {
            float a[8], b[4];
#pragma unroll
            for (int m = 0; m < 8; m++) a[m] = As[k * 128 + ty * 8 + m];
#pragma unroll
            for (int n = 0; n < 4; n++) b[n] = Bs[k * 64 + tx * 4 + n];
#pragma unroll
            for (int m = 0; m < 8; m++)
#pragma unroll
                for (int n = 0; n < 4; n++) acc[m][n] = fmaf(a[m], b[n], acc[m][n]);
        }
        __syncthreads();
    }

    const int col = bn0 + tx * 4;
    float4 bb = *(const float4*)(bias + col);
#pragma unroll
    for (int m = 0; m < 8; m++) {
        int row = bm0 + ty * 8 + m;
        float4 f4 = *(const float4*)(F + (size_t)row * DD + col);
        float s0 = acc[m][0] + bb.x, s1 = acc[m][1] + bb.y;
        float s2 = acc[m][2] + bb.z, s3 = acc[m][3] + bb.w;
        float g0 = f4.x * (1.f / (1.f + __expf(-s0)));
        float g1 = f4.y * (1.f / (1.f + __expf(-s1)));
        float g2 = f4.z * (1.f / (1.f + __expf(-s2)));
        float g3 = f4.w * (1.f / (1.f + __expf(-s3)));
        float4 o;
        o.x = (g0 > 0.3f) ? 0.f : g0;
        o.y = (g1 > 0.3f) ? 0.f : g1;
        o.z = (g2 > 0.3f) ? 0.f : g2;
        o.w = (g3 > 0.3f) ? 0.f : g3;
        *(float4*)(g_comp + (size_t)row * DD + col) = o;
    }
}

// ---------------------------------------------------------------------------
// Row pass: cur_sp -> rw MLP -> dyn -> mean/std(ddof=1)/max -> thr MLP -> mask
// One block handles 16 rows (reuses w_r2 via L1; 64KB fits). 256 thr x 4 cols.
// ---------------------------------------------------------------------------
__global__ __launch_bounds__(256) void k_rowfix(
    const float* __restrict__ wr1, const float* __restrict__ br1,
    const float* __restrict__ wr2, const float* __restrict__ br2,
    const float* __restrict__ wm1, const float* __restrict__ bm1,
    const float* __restrict__ wm2, const float* __restrict__ bm2,
    float* __restrict__ out)
{
    __shared__ float s_red[24];
    __shared__ float s_bc[4];
    const int tid = threadIdx.x;
    const int lane = tid & 31, warp = tid >> 5;

    for (int r = 0; r < 16; ++r) {
        const int row = blockIdx.x * 16 + r;
        const float* crow = g_comp + (size_t)row * DD;
        float4 c4 = *(const float4*)(crow + tid * 4);
        float cv[4] = {c4.x, c4.y, c4.z, c4.w};

        // ---- phase 1: count |comp| < 0.1 ----
        float cnt = 0.f;
#pragma unroll
        for (int n = 0; n < 4; n++) cnt += (fabsf(cv[n]) < 0.1f) ? 1.f : 0.f;
#pragma unroll
        for (int o = 16; o > 0; o >>= 1) cnt += __shfl_down_sync(0xffffffffu, cnt, o);
        if (lane == 0) s_red[warp] = cnt;
        __syncthreads();
        if (warp == 0) {
            float v = (lane < 8) ? s_red[lane] : 0.f;
#pragma unroll
            for (int o = 4; o > 0; o >>= 1) v += __shfl_down_sync(0xffffffffu, v, o);
            if (lane == 0) s_bc[0] = v;
        }
        __syncthreads();
        float cur_sp = s_bc[0] * (1.f / 1024.f);

        // ---- rw MLP: a = relu([cur_sp, 0.1] @ wr1 + br1) ----
        float a[16];
#pragma unroll
        for (int k = 0; k < 16; k++)
            a[k] = fmaxf(fmaf(cur_sp, wr1[k], fmaf(0.1f, wr1[16 + k], br1[k])), 0.f);

        float dyn[4];
        float sum = 0.f, ssq = 0.f, mx = -3.402823466e38f;
#pragma unroll
        for (int n = 0; n < 4; n++) {
            int j = tid * 4 + n;
            float s = br2[j];
#pragma unroll
            for (int k = 0; k < 16; k++) s = fmaf(a[k], wr2[k * DD + j], s);
            float rw = 1.f / (1.f + __expf(-s));
            float d = cv[n] * rw;
            dyn[n] = d;
            sum += d;
            ssq = fmaf(d, d, ssq);
            mx = fmaxf(mx, d);
        }

        // ---- phase 2: reduce sum / sumsq / max ----
#pragma unroll
        for (int o = 16; o > 0; o >>= 1) {
            sum += __shfl_down_sync(0xffffffffu, sum, o);
            ssq += __shfl_down_sync(0xffffffffu, ssq, o);
            mx = fmaxf(mx, __shfl_down_sync(0xffffffffu, mx, o));
        }
        if (lane == 0) {
            s_red[warp * 3 + 0] = sum;
            s_red[warp * 3 + 1] = ssq;
            s_red[warp * 3 + 2] = mx;
        }
        __syncthreads();
        if (warp == 0) {
            float v0 = (lane < 8) ? s_red[lane * 3 + 0] : 0.f;
            float v1 = (lane < 8) ? s_red[lane * 3 + 1] : 0.f;
            float v2 = (lane < 8) ? s_red[lane * 3 + 2] : -3.402823466e38f;
#pragma unroll
            for (int o = 4; o > 0; o >>= 1) {
                v0 += __shfl_down_sync(0xffffffffu, v0, o);
                v1 += __shfl_down_sync(0xffffffffu, v1, o);
                v2 = fmaxf(v2, __shfl_down_sync(0xffffffffu, v2, o));
            }
            if (lane == 0) { s_bc[1] = v0; s_bc[2] = v1; s_bc[3] = v2; }
        }
        __syncthreads();
        float mean = s_bc[1] * (1.f / 1024.f);
        float var = (s_bc[2] - 1024.f * mean * mean) * (1.f / 1023.f);
        var = fmaxf(var, 0.f);
        float sd = sqrtf(var);
        float mxt = s_bc[3];

        // ---- thr MLP: sigmoid(relu([mean,std,max]@wm1+bm1)@wm2+bm2) ----
        float sacc = bm2[0];
#pragma unroll
        for (int k = 0; k < 16; k++) {
            float mk = fmaf(mean, wm1[k], fmaf(sd, wm1[16 + k], fmaf(mxt, wm1[32 + k], bm1[k])));
            mk = fmaxf(mk, 0.f);
            sacc = fmaf(mk, wm2[k], sacc);
        }
        float thr = 1.f / (1.f + __expf(-sacc));

        float4 o;
        o.x = (fabsf(dyn[0]) > thr) ? dyn[0] : 0.f;
        o.y = (fabsf(dyn[1]) > thr) ? dyn[1] : 0.f;
        o.z = (fabsf(dyn[2]) > thr) ? dyn[2] : 0.f;
        o.w = (fabsf(dyn[3]) > thr) ? dyn[3] : 0.f;
        *(float4*)(out + (size_t)row * DD + tid * 4) = o;
        __syncthreads();   // protect s_red/s_bc reuse next row
    }
}

// ---------------------------------------------------------------------------
extern "C" void kernel_launch(void* const* d_in, const int* in_sizes, int n_in,
                              void* d_out, int out_size)
{
    (void)in_sizes; (void)n_in; (void)out_size;
    const float* F   = (const float*)d_in[0];
    const float* wg1 = (const float*)d_in[1];
    const float* bg1 = (const float*)d_in[2];
    const float* wg2 = (const float*)d_in[3];
    const float* bg2 = (const float*)d_in[4];
    // d_in[5..8] (competition_calculator) are provably dead code in the reference.
    const float* wr1 = (const float*)d_in[9];
    const float* br1 = (const float*)d_in[10];
    const float* wr2 = (const float*)d_in[11];
    const float* br2 = (const float*)d_in[12];
    const float* wm1 = (const float*)d_in[13];
    const float* bm1 = (const float*)d_in[14];
    const float* wm2 = (const float*)d_in[15];
    const float* bm2 = (const float*)d_in[16];
    float* out = (float*)d_out;

    k_gemm1<<<dim3(HH / 64, NB / 128), 256>>>(F, wg1, bg1);
    k_gemm2<<<dim3(DD / 64, NB / 128), 256>>>(F, wg2, bg2);
    k_rowfix<<<NB / 16, 256>>>(wr1, br1, wr2, br2, wm1, bm1, wm2, bm2, out);
}

// round 7
// speedup vs baseline: 1.1357x; 1.1357x over previous
#include <cuda_runtime.h>

#define NB 32768
#define DD 1024
#define HH 256

// Scratch (no allocations allowed): h1 = relu(F@Wg1+b)  [32768,256]
// comp = clipped gated features                          [32768,1024]
__device__ float g_h1[(size_t)NB * HH];
__device__ float g_comp[(size_t)NB * DD];

// ---------------------------------------------------------------------------
// GEMM1: h1 = relu(F[32768,1024] @ Wg1[1024,256] + b_g1)   (proven R2 kernel)
// ---------------------------------------------------------------------------
__global__ __launch_bounds__(256) void k_gemm1(const float* __restrict__ A,
                                               const float* __restrict__ W,
                                               const float* __restrict__ bias)
{
    const int K = DD, N = HH;
    __shared__ float As[16 * 128];   // [k][m]
    __shared__ float Bs[16 * 64];    // [k][n]
    const int tid = threadIdx.x;
    const int tx = tid & 15, ty = tid >> 4;
    const int bm0 = blockIdx.y * 128;
    const int bn0 = blockIdx.x * 64;

    float acc[8][4];
#pragma unroll
    for (int m = 0; m < 8; m++)
#pragma unroll
        for (int n = 0; n < 4; n++) acc[m][n] = 0.f;

    const int ar = tid >> 1;
    const int acb = (tid & 1) * 8;
    const int br = tid >> 4;
    const int bc4 = (tid & 15) * 4;

    for (int k0 = 0; k0 < K; k0 += 16) {
        const float* ap = A + (size_t)(bm0 + ar) * K + k0 + acb;
        float4 v0 = *(const float4*)(ap);
        float4 v1 = *(const float4*)(ap + 4);
        As[(acb + 0) * 128 + ar] = v0.x;
        As[(acb + 1) * 128 + ar] = v0.y;
        As[(acb + 2) * 128 + ar] = v0.z;
        As[(acb + 3) * 128 + ar] = v0.w;
        As[(acb + 4) * 128 + ar] = v1.x;
        As[(acb + 5) * 128 + ar] = v1.y;
        As[(acb + 6) * 128 + ar] = v1.z;
        As[(acb + 7) * 128 + ar] = v1.w;
        *(float4*)(Bs + br * 64 + bc4) =
            *(const float4*)(W + (size_t)(k0 + br) * N + bn0 + bc4);
        __syncthreads();
#pragma unroll
        for (int k = 0; k < 16; k++) {
            float a[8], b[4];
#pragma unroll
            for (int m = 0; m < 8; m++) a[m] = As[k * 128 + ty * 8 + m];
#pragma unroll
            for (int n = 0; n < 4; n++) b[n] = Bs[k * 64 + tx * 4 + n];
#pragma unroll
            for (int m = 0; m < 8; m++)
#pragma unroll
                for (int n = 0; n < 4; n++) acc[m][n] = fmaf(a[m], b[n], acc[m][n]);
        }
        __syncthreads();
    }

    const int col = bn0 + tx * 4;
    float4 bb = *(const float4*)(bias + col);
#pragma unroll
    for (int m = 0; m < 8; m++) {
        int row = bm0 + ty * 8 + m;
        float4 o;
        o.x = fmaxf(acc[m][0] + bb.x, 0.f);
        o.y = fmaxf(acc[m][1] + bb.y, 0.f);
        o.z = fmaxf(acc[m][2] + bb.z, 0.f);
        o.w = fmaxf(acc[m][3] + bb.w, 0.f);
        *(float4*)(g_h1 + (size_t)row * N + col) = o;
    }
}

// ---------------------------------------------------------------------------
// GEMM2 + fused epilogue (proven R2 kernel):
//   gw    = sigmoid(h1 @ Wg2 + b_g2);  gated = F * gw
//   comp  = (gated > 0.3) ? 0 : gated      (competition path is dead code)
// ---------------------------------------------------------------------------
__global__ __launch_bounds__(256) void k_gemm2(const float* __restrict__ F,
                                               const float* __restrict__ W,
                                               const float* __restrict__ bias)
{
    const int K = HH, N = DD;
    __shared__ float As[16 * 128];
    __shared__ float Bs[16 * 64];
    const int tid = threadIdx.x;
    const int tx = tid & 15, ty = tid >> 4;
    const int bm0 = blockIdx.y * 128;
    const int bn0 = blockIdx.x * 64;

    float acc[8][4];
#pragma unroll
    for (int m = 0; m < 8; m++)
#pragma unroll
        for (int n = 0; n < 4; n++) acc[m][n] = 0.f;

    const int ar = tid >> 1;
    const int acb = (tid & 1) * 8;
    const int br = tid >> 4;
    const int bc4 = (tid & 15) * 4;

    for (int k0 = 0; k0 < K; k0 += 16) {
        const float* ap = g_h1 + (size_t)(bm0 + ar) * K + k0 + acb;
        float4 v0 = *(const float4*)(ap);
        float4 v1 = *(const float4*)(ap + 4);
        As[(acb + 0) * 128 + ar] = v0.x;
        As[(acb + 1) * 128 + ar] = v0.y;
        As[(acb + 2) * 128 + ar] = v0.z;
        As[(acb + 3) * 128 + ar] = v0.w;
        As[(acb + 4) * 128 + ar] = v1.x;
        As[(acb + 5) * 128 + ar] = v1.y;
        As[(acb + 6) * 128 + ar] = v1.z;
        As[(acb + 7) * 128 + ar] = v1.w;
        *(float4*)(Bs + br * 64 + bc4) =
            *(const float4*)(W + (size_t)(k0 + br) * N + bn0 + bc4);
        __syncthreads();
#pragma unroll
        for (int k = 0; k < 16; k++) {
            float a[8], b[4];
#pragma unroll
            for (int m = 0; m < 8; m++) a[m] = As[k * 128 + ty * 8 + m];
#pragma unroll
            for (int n = 0; n < 4; n++) b[n] = Bs[k * 64 + tx * 4 + n];
#pragma unroll
            for (int m = 0; m < 8; m++)
#pragma unroll
                for (int n = 0; n < 4; n++) acc[m][n] = fmaf(a[m], b[n], acc[m][n]);
        }
        __syncthreads();
    }

    const int col = bn0 + tx * 4;
    float4 bb = *(const float4*)(bias + col);
#pragma unroll
    for (int m = 0; m < 8; m++) {
        int row = bm0 + ty * 8 + m;
        float4 f4 = *(const float4*)(F + (size_t)row * DD + col);
        float s0 = acc[m][0] + bb.x, s1 = acc[m][1] + bb.y;
        float s2 = acc[m][2] + bb.z, s3 = acc[m][3] + bb.w;
        float g0 = f4.x * (1.f / (1.f + __expf(-s0)));
        float g1 = f4.y * (1.f / (1.f + __expf(-s1)));
        float g2 = f4.z * (1.f / (1.f + __expf(-s2)));
        float g3 = f4.w * (1.f / (1.f + __expf(-s3)));
        float4 o;
        o.x = (g0 > 0.3f) ? 0.f : g0;
        o.y = (g1 > 0.3f) ? 0.f : g1;
        o.z = (g2 > 0.3f) ? 0.f : g2;
        o.w = (g3 > 0.3f) ? 0.f : g3;
        *(float4*)(g_comp + (size_t)row * DD + col) = o;
    }
}

// ---------------------------------------------------------------------------
// Row pass v2: warp-per-row, shfl-only reductions (under test this round)
// ---------------------------------------------------------------------------
__global__ __launch_bounds__(256) void k_rowfix(
    const float* __restrict__ wr1, const float* __restrict__ br1,
    const float* __restrict__ wr2, const float* __restrict__ br2,
    const float* __restrict__ wm1, const float* __restrict__ bm1,
    const float* __restrict__ wm2, const float* __restrict__ bm2,
    float* __restrict__ out) {
    int tid = threadIdx.x, wid = tid >> 5, lane = tid & 31;
    int row = blockIdx.x * 8 + wid;
    const float4* crow = (const float4*)(g_comp + (size_t)row * DD);
    float4 c[8];
#pragma unroll
    for (int j = 0; j < 8; j++) c[j] = crow[j * 32 + lane];

    float cnt = 0.f;
#pragma unroll
    for (int j = 0; j < 8; j++) {
        cnt += (fabsf(c[j].x) < 0.1f) ? 1.f : 0.f;
        cnt += (fabsf(c[j].y) < 0.1f) ? 1.f : 0.f;
        cnt += (fabsf(c[j].z) < 0.1f) ? 1.f : 0.f;
        cnt += (fabsf(c[j].w) < 0.1f) ? 1.f : 0.f;
    }
#pragma unroll
    for (int o = 16; o > 0; o >>= 1) cnt += __shfl_xor_sync(0xffffffffu, cnt, o);
    float cur_sp = cnt * (1.f / 1024.f);

    float a[16];
#pragma unroll
    for (int k = 0; k < 16; k++)
        a[k] = fmaxf(fmaf(cur_sp, wr1[k], fmaf(0.1f, wr1[16 + k], br1[k])), 0.f);

    float dyn[32];
    float sum = 0.f, ssq = 0.f, mx = -3.402823466e38f;
#pragma unroll
    for (int j = 0; j < 8; j++) {
        float cv[4] = {c[j].x, c[j].y, c[j].z, c[j].w};
#pragma unroll
        for (int q = 0; q < 4; q++) {
            int jg = (j * 32 + lane) * 4 + q;
            float s = br2[jg];
#pragma unroll
            for (int k = 0; k < 16; k++) s = fmaf(a[k], wr2[k * DD + jg], s);
            float rw = 1.f / (1.f + __expf(-s));
            float d = cv[q] * rw;
            dyn[j * 4 + q] = d;
            sum += d;
            ssq = fmaf(d, d, ssq);
            mx = fmaxf(mx, d);
        }
    }
#pragma unroll
    for (int o = 16; o > 0; o >>= 1) {
        sum += __shfl_xor_sync(0xffffffffu, sum, o);
        ssq += __shfl_xor_sync(0xffffffffu, ssq, o);
        mx = fmaxf(mx, __shfl_xor_sync(0xffffffffu, mx, o));
    }
    float mean = sum * (1.f / 1024.f);
    float var = fmaxf((ssq - 1024.f * mean * mean) * (1.f / 1023.f), 0.f);
    float sd = sqrtf(var);

    float sacc = bm2[0];
#pragma unroll
    for (int k = 0; k < 16; k++) {
        float mk = fmaf(mean, wm1[k], fmaf(sd, wm1[16 + k], fmaf(mx, wm1[32 + k], bm1[k])));
        sacc = fmaf(fmaxf(mk, 0.f), wm2[k], sacc);
    }
    float thr = 1.f / (1.f + __expf(-sacc));

    float4* orow = (float4*)(out + (size_t)row * DD);
#pragma unroll
    for (int j = 0; j < 8; j++) {
        float4 o;
        o.x = (fabsf(dyn[j * 4 + 0]) > thr) ? dyn[j * 4 + 0] : 0.f;
        o.y = (fabsf(dyn[j * 4 + 1]) > thr) ? dyn[j * 4 + 1] : 0.f;
        o.z = (fabsf(dyn[j * 4 + 2]) > thr) ? dyn[j * 4 + 2] : 0.f;
        o.w = (fabsf(dyn[j * 4 + 3]) > thr) ? dyn[j * 4 + 3] : 0.f;
        orow[j * 32 + lane] = o;
    }
}

// ---------------------------------------------------------------------------
extern "C" void kernel_launch(void* const* d_in, const int* in_sizes, int n_in,
                              void* d_out, int out_size)
{
    (void)in_sizes; (void)n_in; (void)out_size;
    const float* F   = (const float*)d_in[0];
    const float* wg1 = (const float*)d_in[1];
    const float* bg1 = (const float*)d_in[2];
    const float* wg2 = (const float*)d_in[3];
    const float* bg2 = (const float*)d_in[4];
    // d_in[5..8] (competition_calculator) are provably dead code in the reference.
    const float* wr1 = (const float*)d_in[9];
    const float* br1 = (const float*)d_in[10];
    const float* wr2 = (const float*)d_in[11];
    const float* br2 = (const float*)d_in[12];
    const float* wm1 = (const float*)d_in[13];
    const float* bm1 = (const float*)d_in[14];
    const float* wm2 = (const float*)d_in[15];
    const float* bm2 = (const float*)d_in[16];
    float* out = (float*)d_out;

    k_gemm1<<<dim3(HH / 64, NB / 128), 256>>>(F, wg1, bg1);
    k_gemm2<<<dim3(DD / 64, NB / 128), 256>>>(F, wg2, bg2);
    k_rowfix<<<NB / 8, 256>>>(wr1, br1, wr2, br2, wm1, bm1, wm2, bm2, out);
}